// round 9
// baseline (speedup 1.0000x reference)
#include <cuda_runtime.h>
#include <math.h>
#include <stdint.h>

// Problem dims
#define Bdim   4
#define Sdim   2048
#define DMdim  1024
#define Hdim   16
#define DPT    64
#define BHdim  (Bdim*Hdim)

#define OUT_ELEMS  (Bdim*Sdim*DMdim)                 // 8388608
#define ATTN_ELEMS ((long long)BHdim*Sdim*Sdim)      // 268435456
#define CHUNK_BH   4
#define NCTILE     16                                 // Sdim/128 col tiles

// Scratch (allocation-free: __device__ globals). ~206 MB total.
__device__ float g_qh[(size_t)BHdim*Sdim*DPT];
__device__ float g_kh[(size_t)BHdim*Sdim*DPT];
__device__ float g_vh[(size_t)BHdim*Sdim*DPT];
__device__ float g_concat[(size_t)Bdim*Sdim*DMdim];
__device__ float g_psum[(size_t)BHdim*Sdim*NCTILE];  // per-(row, col-tile) exp sums
__device__ float g_attn_chunk[(size_t)CHUNK_BH*Sdim*Sdim];

// ---------------------------------------------------------------------------
__device__ __forceinline__ uint32_t f2tf(float x) {
    uint32_t r;
    asm("cvt.rna.tf32.f32 %0, %1;" : "=r"(r) : "f"(x));
    return r;
}

__device__ __forceinline__ void mma8(float* c, const uint32_t* a, const uint32_t* b) {
    asm volatile(
        "mma.sync.aligned.m16n8k8.row.col.f32.tf32.tf32.f32 "
        "{%0,%1,%2,%3},{%4,%5,%6,%7},{%8,%9},{%0,%1,%2,%3};\n"
        : "+f"(c[0]), "+f"(c[1]), "+f"(c[2]), "+f"(c[3])
        : "r"(a[0]), "r"(a[1]), "r"(a[2]), "r"(a[3]), "r"(b[0]), "r"(b[1]));
}

// ---------------------------------------------------------------------------
// tf32 GEMM: C(128x128/block) = A(MxK) @ W(NxK)^T (+bias), K=1024  (R7 version)
// EPI: 0 = dense row-major (M x DMdim), 1 = head-scatter to (B,H,S,DPT)
// ---------------------------------------------------------------------------
template<int EPI>
__global__ void __launch_bounds__(256, 2)
gemm1024_tf32(const float* __restrict__ A, const float* __restrict__ W,
              const float* __restrict__ bias, float* __restrict__ out)
{
    const int K = 1024;
    __shared__ uint32_t As[16][136];   // [k][m]
    __shared__ uint32_t Bs[16][136];   // [k][n]
    int t = threadIdx.x, lane = t & 31, w = t >> 5;
    int q = lane & 3, r = lane >> 2;
    int m0 = blockIdx.y * 128, n0 = blockIdx.x * 128;
    int wm = (w & 1) * 64, wn = (w >> 1) * 32;
    int lr = t >> 1, lc = (t & 1) * 4;
    const float* Ap = A + (size_t)(m0 + lr) * K + lc;
    const float* Wp = W + (size_t)(n0 + lr) * K + lc;

    float acc[4][4][4];
    #pragma unroll
    for (int i = 0; i < 4; i++)
        #pragma unroll
        for (int j = 0; j < 4; j++)
            #pragma unroll
            for (int v = 0; v < 4; v++) acc[i][j][v] = 0.f;

    float4 pa0 = *(const float4*)Ap,      pa1 = *(const float4*)(Ap + 8);
    float4 pb0 = *(const float4*)Wp,      pb1 = *(const float4*)(Wp + 8);

    for (int kt = 0; kt < K; kt += 16) {
        __syncthreads();
        As[lc+0][lr]=f2tf(pa0.x); As[lc+1][lr]=f2tf(pa0.y); As[lc+2][lr]=f2tf(pa0.z); As[lc+3][lr]=f2tf(pa0.w);
        As[lc+8][lr]=f2tf(pa1.x); As[lc+9][lr]=f2tf(pa1.y); As[lc+10][lr]=f2tf(pa1.z); As[lc+11][lr]=f2tf(pa1.w);
        Bs[lc+0][lr]=f2tf(pb0.x); Bs[lc+1][lr]=f2tf(pb0.y); Bs[lc+2][lr]=f2tf(pb0.z); Bs[lc+3][lr]=f2tf(pb0.w);
        Bs[lc+8][lr]=f2tf(pb1.x); Bs[lc+9][lr]=f2tf(pb1.y); Bs[lc+10][lr]=f2tf(pb1.z); Bs[lc+11][lr]=f2tf(pb1.w);
        __syncthreads();
        if (kt + 16 < K) {
            pa0 = *(const float4*)(Ap + kt + 16); pa1 = *(const float4*)(Ap + kt + 24);
            pb0 = *(const float4*)(Wp + kt + 16); pb1 = *(const float4*)(Wp + kt + 24);
        }
        #pragma unroll
        for (int ks = 0; ks < 2; ks++) {
            uint32_t af[4][4], bf[4][2];
            #pragma unroll
            for (int mt = 0; mt < 4; mt++) {
                af[mt][0] = As[ks*8 + q][wm + mt*16 + r];
                af[mt][1] = As[ks*8 + q][wm + mt*16 + 8 + r];
                af[mt][2] = As[ks*8 + 4 + q][wm + mt*16 + r];
                af[mt][3] = As[ks*8 + 4 + q][wm + mt*16 + 8 + r];
            }
            #pragma unroll
            for (int nt = 0; nt < 4; nt++) {
                bf[nt][0] = Bs[ks*8 + q][wn + nt*8 + r];
                bf[nt][1] = Bs[ks*8 + 4 + q][wn + nt*8 + r];
            }
            #pragma unroll
            for (int mt = 0; mt < 4; mt++)
                #pragma unroll
                for (int nt = 0; nt < 4; nt++)
                    mma8(acc[mt][nt], af[mt], bf[nt]);
        }
    }

    #pragma unroll
    for (int mt = 0; mt < 4; mt++) {
        #pragma unroll
        for (int nt = 0; nt < 4; nt++) {
            int m = m0 + wm + mt*16 + r;
            int n = n0 + wn + nt*8 + 2*q;
            float* a4 = acc[mt][nt];
            float bv0 = bias[n], bv1 = bias[n+1];
            if (EPI == 0) {
                *(float2*)&out[(size_t)m*DMdim + n]     = make_float2(a4[0]+bv0, a4[1]+bv1);
                *(float2*)&out[(size_t)(m+8)*DMdim + n] = make_float2(a4[2]+bv0, a4[3]+bv1);
            } else {
                int bb = m >> 11, s = m & 2047, h = n >> 6, d = n & 63;
                size_t base = ((size_t)(bb*Hdim + h)) * Sdim;
                *(float2*)&out[(base + s)*DPT + d]     = make_float2(a4[0]+bv0, a4[1]+bv1);
                *(float2*)&out[(base + s + 8)*DPT + d] = make_float2(a4[2]+bv0, a4[3]+bv1);
            }
        }
    }
}

// ---------------------------------------------------------------------------
// QK^T (tf32) + fused exp, COALESCED epilogue via smem transpose.
// P = exp(Q@K^T * 0.125 + mask*(-1e9)); unnormalized P -> attn; row-tile
// partial sums -> g_psum.
// ---------------------------------------------------------------------------
#define AS(k,i) sbuf[(size_t)(k)*136 + (i)]
#define BS(k,i) sbuf[2176 + (size_t)(k)*136 + (i)]

__global__ void __launch_bounds__(256, 2)
qk_tf32(const float* __restrict__ mask, float* __restrict__ attn, int bh_base)
{
    const int K = DPT;
    __shared__ uint32_t sbuf[2*16*136];   // 17408 B: mainloop A/B; epilogue [32][132] f32
    int t = threadIdx.x, lane = t & 31, w = t >> 5;
    int q = lane & 3, r = lane >> 2;
    int zl = blockIdx.z, bh = bh_base + zl;
    int m0 = blockIdx.y * 128, n0 = blockIdx.x * 128;
    int wm = (w & 1) * 64, wn = (w >> 1) * 32;
    int lr = t >> 1, lc = (t & 1) * 4;
    const float* Q  = g_qh + (size_t)bh * Sdim * DPT;
    const float* Kh = g_kh + (size_t)bh * Sdim * DPT;
    const float* Ap = Q  + (size_t)(m0 + lr) * K + lc;
    const float* Wp = Kh + (size_t)(n0 + lr) * K + lc;

    float acc[4][4][4];
    #pragma unroll
    for (int i = 0; i < 4; i++)
        #pragma unroll
        for (int j = 0; j < 4; j++)
            #pragma unroll
            for (int v = 0; v < 4; v++) acc[i][j][v] = 0.f;

    float4 pa0 = *(const float4*)Ap, pa1 = *(const float4*)(Ap + 8);
    float4 pb0 = *(const float4*)Wp, pb1 = *(const float4*)(Wp + 8);

    #pragma unroll
    for (int kt = 0; kt < K; kt += 16) {
        __syncthreads();
        AS(lc+0,lr)=f2tf(pa0.x); AS(lc+1,lr)=f2tf(pa0.y); AS(lc+2,lr)=f2tf(pa0.z); AS(lc+3,lr)=f2tf(pa0.w);
        AS(lc+8,lr)=f2tf(pa1.x); AS(lc+9,lr)=f2tf(pa1.y); AS(lc+10,lr)=f2tf(pa1.z); AS(lc+11,lr)=f2tf(pa1.w);
        BS(lc+0,lr)=f2tf(pb0.x); BS(lc+1,lr)=f2tf(pb0.y); BS(lc+2,lr)=f2tf(pb0.z); BS(lc+3,lr)=f2tf(pb0.w);
        BS(lc+8,lr)=f2tf(pb1.x); BS(lc+9,lr)=f2tf(pb1.y); BS(lc+10,lr)=f2tf(pb1.z); BS(lc+11,lr)=f2tf(pb1.w);
        __syncthreads();
        if (kt + 16 < K) {
            pa0 = *(const float4*)(Ap + kt + 16); pa1 = *(const float4*)(Ap + kt + 24);
            pb0 = *(const float4*)(Wp + kt + 16); pb1 = *(const float4*)(Wp + kt + 24);
        }
        #pragma unroll
        for (int ks = 0; ks < 2; ks++) {
            uint32_t af[4][4], bf[4][2];
            #pragma unroll
            for (int mt = 0; mt < 4; mt++) {
                af[mt][0] = AS(ks*8 + q,     wm + mt*16 + r);
                af[mt][1] = AS(ks*8 + q,     wm + mt*16 + 8 + r);
                af[mt][2] = AS(ks*8 + 4 + q, wm + mt*16 + r);
                af[mt][3] = AS(ks*8 + 4 + q, wm + mt*16 + 8 + r);
            }
            #pragma unroll
            for (int nt = 0; nt < 4; nt++) {
                bf[nt][0] = BS(ks*8 + q,     wn + nt*8 + r);
                bf[nt][1] = BS(ks*8 + 4 + q, wn + nt*8 + r);
            }
            #pragma unroll
            for (int mt = 0; mt < 4; mt++)
                #pragma unroll
                for (int nt = 0; nt < 4; nt++)
                    mma8(acc[mt][nt], af[mt], bf[nt]);
        }
    }

    // ---- coalesced epilogue: 4 groups of 32 rows through smem ----
    int erow = t >> 3, ecol = (t & 7) * 16;
    float mk[16];
    {
        const float* mbase = mask + (size_t)(bh >> 4) * Sdim + n0 + ecol;
        #pragma unroll
        for (int j = 0; j < 16; j += 4) {
            float4 mv = *(const float4*)(mbase + j);
            mk[j+0] = mv.x * (-1e9f); mk[j+1] = mv.y * (-1e9f);
            mk[j+2] = mv.z * (-1e9f); mk[j+3] = mv.w * (-1e9f);
        }
    }
    float* ep = (float*)sbuf;            // [32][132]
    float* orow = attn + (size_t)zl * Sdim * Sdim;

    #pragma unroll
    for (int g = 0; g < 4; g++) {
        __syncthreads();
        if ((wm >> 6) == (g >> 1)) {     // warps owning this 32-row group
            int mt0 = (g & 1) * 2;
            #pragma unroll
            for (int mi = 0; mi < 2; mi++) {
                float* a0 = acc[mt0 + mi][0];
                #pragma unroll
                for (int nt = 0; nt < 4; nt++) {
                    float* a4 = acc[mt0 + mi][nt];
                    int rowa = mi*16 + r;
                    int col  = wn + nt*8 + 2*q;
                    *(float2*)&ep[rowa*132 + col]     = make_float2(a4[0], a4[1]);
                    *(float2*)&ep[(rowa+8)*132 + col] = make_float2(a4[2], a4[3]);
                }
                (void)a0;
            }
        }
        __syncthreads();
        float rsum = 0.f;
        float4 outv[4];
        #pragma unroll
        for (int j = 0; j < 4; j++) {
            float4 xv = *(const float4*)&ep[erow*132 + ecol + 4*j];
            float p0 = __expf(xv.x*0.125f + mk[4*j+0]);
            float p1 = __expf(xv.y*0.125f + mk[4*j+1]);
            float p2 = __expf(xv.z*0.125f + mk[4*j+2]);
            float p3 = __expf(xv.w*0.125f + mk[4*j+3]);
            rsum += (p0 + p1) + (p2 + p3);
            outv[j] = make_float4(p0, p1, p2, p3);
        }
        size_t gbase = (size_t)(m0 + g*32 + erow) * Sdim + n0 + ecol;
        #pragma unroll
        for (int j = 0; j < 4; j++)
            *(float4*)&orow[gbase + 4*j] = outv[j];
        rsum += __shfl_xor_sync(0xffffffffu, rsum, 1);
        rsum += __shfl_xor_sync(0xffffffffu, rsum, 2);
        rsum += __shfl_xor_sync(0xffffffffu, rsum, 4);
        if ((t & 7) == 0)
            g_psum[((size_t)bh * Sdim + m0 + g*32 + erow) * NCTILE + blockIdx.x] = rsum;
    }
}

// ---------------------------------------------------------------------------
// PV (tf32) + fused normalize (R7 version): inv = 1/rowsum; normalized P
// written back to attn in place; ctx = Pn @ V into g_concat.
// ---------------------------------------------------------------------------
__global__ void __launch_bounds__(256, 2)
pv_tf32(float* __restrict__ attn, int bh_base)
{
    __shared__ uint32_t Ps[32][136];   // [k][m]
    __shared__ uint32_t Vs[32][72];    // [k][n]
    __shared__ float sinv[128];
    int t = threadIdx.x, lane = t & 31, w = t >> 5;
    int q = lane & 3, r = lane >> 2;
    int zl = blockIdx.y, bh = bh_base + zl;
    int m0 = blockIdx.x * 128;
    int wm = (w & 3) * 32, wn = (w >> 2) * 32;
    float* P = attn + (size_t)zl * Sdim * Sdim;
    const float* V = g_vh + (size_t)bh * Sdim * DPT;

    if (t < 128) {
        const float* pp = &g_psum[((size_t)bh * Sdim + m0 + t) * NCTILE];
        float s = 0.f;
        #pragma unroll
        for (int i = 0; i < NCTILE; i++) s += pp[i];
        sinv[t] = 1.0f / s;
    }
    __syncthreads();

    int lr = t >> 1, lc = (t & 1) * 16;
    float* Pp = P + (size_t)(m0 + lr) * Sdim + lc;
    int vr = t >> 3, vc = (t & 7) * 8;
    const float* Vp = V + (size_t)vr * DPT + vc;
    float inv_r = sinv[lr];

    float acc[2][4][4];
    #pragma unroll
    for (int i = 0; i < 2; i++)
        #pragma unroll
        for (int j = 0; j < 4; j++)
            #pragma unroll
            for (int v = 0; v < 4; v++) acc[i][j][v] = 0.f;

    float4 pa[4];
    #pragma unroll
    for (int i = 0; i < 4; i++) pa[i] = *(const float4*)(Pp + 4*i);
    float4 pv0 = *(const float4*)(Vp);
    float4 pv1 = *(const float4*)(Vp + 4);

    for (int kt = 0; kt < Sdim; kt += 32) {
        float4 sa[4];
        #pragma unroll
        for (int i = 0; i < 4; i++) {
            sa[i].x = pa[i].x * inv_r; sa[i].y = pa[i].y * inv_r;
            sa[i].z = pa[i].z * inv_r; sa[i].w = pa[i].w * inv_r;
        }
        #pragma unroll
        for (int i = 0; i < 4; i++)
            *(float4*)(Pp + kt + 4*i) = sa[i];

        __syncthreads();
        #pragma unroll
        for (int i = 0; i < 4; i++) {
            int kk = lc + 4*i;
            Ps[kk+0][lr] = f2tf(sa[i].x); Ps[kk+1][lr] = f2tf(sa[i].y);
            Ps[kk+2][lr] = f2tf(sa[i].z); Ps[kk+3][lr] = f2tf(sa[i].w);
        }
        Vs[vr][vc+0] = f2tf(pv0.x); Vs[vr][vc+1] = f2tf(pv0.y);
        Vs[vr][vc+2] = f2tf(pv0.z); Vs[vr][vc+3] = f2tf(pv0.w);
        Vs[vr][vc+4] = f2tf(pv1.x); Vs[vr][vc+5] = f2tf(pv1.y);
        Vs[vr][vc+6] = f2tf(pv1.z); Vs[vr][vc+7] = f2tf(pv1.w);
        __syncthreads();
        if (kt + 32 < Sdim) {
            #pragma unroll
            for (int i = 0; i < 4; i++) pa[i] = *(const float4*)(Pp + kt + 32 + 4*i);
            pv0 = *(const float4*)(Vp + (size_t)(kt + 32) * DPT);
            pv1 = *(const float4*)(Vp + (size_t)(kt + 32) * DPT + 4);
        }
        #pragma unroll
        for (int ks = 0; ks < 4; ks++) {
            uint32_t af[2][4], bf[4][2];
            #pragma unroll
            for (int mt = 0; mt < 2; mt++) {
                af[mt][0] = Ps[ks*8 + q][wm + mt*16 + r];
                af[mt][1] = Ps[ks*8 + q][wm + mt*16 + 8 + r];
                af[mt][2] = Ps[ks*8 + 4 + q][wm + mt*16 + r];
                af[mt][3] = Ps[ks*8 + 4 + q][wm + mt*16 + 8 + r];
            }
            #pragma unroll
            for (int nt = 0; nt < 4; nt++) {
                bf[nt][0] = Vs[ks*8 + q][wn + nt*8 + r];
                bf[nt][1] = Vs[ks*8 + 4 + q][wn + nt*8 + r];
            }
            #pragma unroll
            for (int mt = 0; mt < 2; mt++)
                #pragma unroll
                for (int nt = 0; nt < 4; nt++)
                    mma8(acc[mt][nt], af[mt], bf[nt]);
        }
    }

    int bb = bh >> 4, h = bh & 15;
    #pragma unroll
    for (int mt = 0; mt < 2; mt++) {
        #pragma unroll
        for (int nt = 0; nt < 4; nt++) {
            int s = m0 + wm + mt*16 + r;
            int dcol = wn + nt*8 + 2*q;
            float* a4 = acc[mt][nt];
            size_t base = ((size_t)bb * Sdim + s) * DMdim + h*DPT + dcol;
            *(float2*)&g_concat[base]            = make_float2(a4[0], a4[1]);
            *(float2*)&g_concat[base + 8*DMdim]  = make_float2(a4[2], a4[3]);
        }
    }
}

// ---------------------------------------------------------------------------
extern "C" void kernel_launch(void* const* d_in, const int* in_sizes, int n_in,
                              void* d_out, int out_size)
{
    const float* v_in    = (const float*)d_in[0];
    const float* k_in    = (const float*)d_in[1];
    const float* q_in    = (const float*)d_in[2];
    const float* mask    = (const float*)d_in[3];
    const float* wq_w    = (const float*)d_in[4];
    const float* wq_b    = (const float*)d_in[5];
    const float* wk_w    = (const float*)d_in[6];
    const float* wk_b    = (const float*)d_in[7];
    const float* wv_w    = (const float*)d_in[8];
    const float* wv_b    = (const float*)d_in[9];
    const float* dense_w = (const float*)d_in[10];
    const float* dense_b = (const float*)d_in[11];

    float *qh, *kh, *vh, *concat, *attn_chunk;
    cudaGetSymbolAddress((void**)&qh, g_qh);
    cudaGetSymbolAddress((void**)&kh, g_kh);
    cudaGetSymbolAddress((void**)&vh, g_vh);
    cudaGetSymbolAddress((void**)&concat, g_concat);
    cudaGetSymbolAddress((void**)&attn_chunk, g_attn_chunk);

    float* out = (float*)d_out;
    int attn_in_out = ((long long)out_size >= (long long)OUT_ELEMS + ATTN_ELEMS);

    dim3 blk(256);
    dim3 g_gemm(DMdim / 128, (Bdim * Sdim) / 128);   // (8, 64)

    gemm1024_tf32<1><<<g_gemm, blk>>>(q_in, wq_w, wq_b, qh);
    gemm1024_tf32<1><<<g_gemm, blk>>>(k_in, wk_w, wk_b, kh);
    gemm1024_tf32<1><<<g_gemm, blk>>>(v_in, wv_w, wv_b, vh);

    if (attn_in_out) {
        float* attn = out + OUT_ELEMS;
        qk_tf32<<<dim3(NCTILE, Sdim/128, BHdim), blk>>>(mask, attn, 0);
        pv_tf32<<<dim3(Sdim/128, BHdim), blk>>>(attn, 0);
    } else {
        for (int c = 0; c < BHdim; c += CHUNK_BH) {
            qk_tf32<<<dim3(NCTILE, Sdim/128, CHUNK_BH), blk>>>(mask, attn_chunk, c);
            pv_tf32<<<dim3(Sdim/128, CHUNK_BH), blk>>>(attn_chunk, c);
        }
    }

    gemm1024_tf32<0><<<g_gemm, blk>>>(concat, dense_w, dense_b, out);
}

// round 10
// speedup vs baseline: 1.1222x; 1.1222x over previous
#include <cuda_runtime.h>
#include <math.h>
#include <stdint.h>

// Problem dims
#define Bdim   4
#define Sdim   2048
#define DMdim  1024
#define Hdim   16
#define DPT    64
#define BHdim  (Bdim*Hdim)

#define OUT_ELEMS  (Bdim*Sdim*DMdim)                 // 8388608
#define ATTN_ELEMS ((long long)BHdim*Sdim*Sdim)      // 268435456
#define CHUNK_BH   4
#define NCTILE     16                                 // Sdim/128 col tiles

// Scratch (allocation-free: __device__ globals). ~206 MB total.
__device__ float g_qh[(size_t)BHdim*Sdim*DPT];
__device__ float g_kh[(size_t)BHdim*Sdim*DPT];
__device__ float g_vh[(size_t)BHdim*Sdim*DPT];
__device__ float g_concat[(size_t)Bdim*Sdim*DMdim];
__device__ float g_psum[(size_t)BHdim*Sdim*NCTILE];  // per-(row, col-tile) exp sums
__device__ float g_attn_chunk[(size_t)CHUNK_BH*Sdim*Sdim];

// ---------------------------------------------------------------------------
__device__ __forceinline__ uint32_t f2tf(float x) {
    uint32_t r;
    asm("cvt.rna.tf32.f32 %0, %1;" : "=r"(r) : "f"(x));
    return r;
}

__device__ __forceinline__ void mma8(float* c, const uint32_t* a, const uint32_t* b) {
    asm volatile(
        "mma.sync.aligned.m16n8k8.row.col.f32.tf32.tf32.f32 "
        "{%0,%1,%2,%3},{%4,%5,%6,%7},{%8,%9},{%0,%1,%2,%3};\n"
        : "+f"(c[0]), "+f"(c[1]), "+f"(c[2]), "+f"(c[3])
        : "r"(a[0]), "r"(a[1]), "r"(a[2]), "r"(a[3]), "r"(b[0]), "r"(b[1]));
}

// ---------------------------------------------------------------------------
// tf32 GEMM: C(128x128/block) = A(MxK) @ W(NxK)^T (+bias), K=1024, BK=16
// DOUBLE-BUFFERED smem: one __syncthreads per k-iteration; STS of tile k+1
// overlaps MMA of tile k.
// EPI: 0 = dense row-major (M x DMdim), 1 = head-scatter to (B,H,S,DPT)
// ---------------------------------------------------------------------------
template<int EPI>
__global__ void __launch_bounds__(256, 2)
gemm1024_tf32(const float* __restrict__ A, const float* __restrict__ W,
              const float* __restrict__ bias, float* __restrict__ out)
{
    const int K = 1024;
    __shared__ uint32_t As[2][16][136];   // 17 KB
    __shared__ uint32_t Bs[2][16][136];   // 17 KB
    int t = threadIdx.x, lane = t & 31, w = t >> 5;
    int q = lane & 3, r = lane >> 2;
    int m0 = blockIdx.y * 128, n0 = blockIdx.x * 128;
    int wm = (w & 1) * 64, wn = (w >> 1) * 32;
    int lr = t >> 1, lc = (t & 1) * 4;
    const float* Ap = A + (size_t)(m0 + lr) * K + lc;
    const float* Wp = W + (size_t)(n0 + lr) * K + lc;

    float acc[4][4][4];
    #pragma unroll
    for (int i = 0; i < 4; i++)
        #pragma unroll
        for (int j = 0; j < 4; j++)
            #pragma unroll
            for (int v = 0; v < 4; v++) acc[i][j][v] = 0.f;

    // stage k-tile 0 into buffer 0
    {
        float4 a0 = *(const float4*)Ap,  a1 = *(const float4*)(Ap + 8);
        float4 b0 = *(const float4*)Wp,  b1 = *(const float4*)(Wp + 8);
        As[0][lc+0][lr]=f2tf(a0.x); As[0][lc+1][lr]=f2tf(a0.y); As[0][lc+2][lr]=f2tf(a0.z); As[0][lc+3][lr]=f2tf(a0.w);
        As[0][lc+8][lr]=f2tf(a1.x); As[0][lc+9][lr]=f2tf(a1.y); As[0][lc+10][lr]=f2tf(a1.z); As[0][lc+11][lr]=f2tf(a1.w);
        Bs[0][lc+0][lr]=f2tf(b0.x); Bs[0][lc+1][lr]=f2tf(b0.y); Bs[0][lc+2][lr]=f2tf(b0.z); Bs[0][lc+3][lr]=f2tf(b0.w);
        Bs[0][lc+8][lr]=f2tf(b1.x); Bs[0][lc+9][lr]=f2tf(b1.y); Bs[0][lc+10][lr]=f2tf(b1.z); Bs[0][lc+11][lr]=f2tf(b1.w);
    }
    __syncthreads();

    int cur = 0;
    for (int kt = 0; kt < K; kt += 16) {
        float4 a0, a1, b0, b1;
        bool nxt = (kt + 16 < K);
        if (nxt) {
            a0 = *(const float4*)(Ap + kt + 16); a1 = *(const float4*)(Ap + kt + 24);
            b0 = *(const float4*)(Wp + kt + 16); b1 = *(const float4*)(Wp + kt + 24);
        }
        #pragma unroll
        for (int ks = 0; ks < 2; ks++) {
            uint32_t af[4][4], bf[4][2];
            #pragma unroll
            for (int mt = 0; mt < 4; mt++) {
                af[mt][0] = As[cur][ks*8 + q][wm + mt*16 + r];
                af[mt][1] = As[cur][ks*8 + q][wm + mt*16 + 8 + r];
                af[mt][2] = As[cur][ks*8 + 4 + q][wm + mt*16 + r];
                af[mt][3] = As[cur][ks*8 + 4 + q][wm + mt*16 + 8 + r];
            }
            #pragma unroll
            for (int nt = 0; nt < 4; nt++) {
                bf[nt][0] = Bs[cur][ks*8 + q][wn + nt*8 + r];
                bf[nt][1] = Bs[cur][ks*8 + 4 + q][wn + nt*8 + r];
            }
            #pragma unroll
            for (int mt = 0; mt < 4; mt++)
                #pragma unroll
                for (int nt = 0; nt < 4; nt++)
                    mma8(acc[mt][nt], af[mt], bf[nt]);
        }
        if (nxt) {
            int nb = cur ^ 1;
            As[nb][lc+0][lr]=f2tf(a0.x); As[nb][lc+1][lr]=f2tf(a0.y); As[nb][lc+2][lr]=f2tf(a0.z); As[nb][lc+3][lr]=f2tf(a0.w);
            As[nb][lc+8][lr]=f2tf(a1.x); As[nb][lc+9][lr]=f2tf(a1.y); As[nb][lc+10][lr]=f2tf(a1.z); As[nb][lc+11][lr]=f2tf(a1.w);
            Bs[nb][lc+0][lr]=f2tf(b0.x); Bs[nb][lc+1][lr]=f2tf(b0.y); Bs[nb][lc+2][lr]=f2tf(b0.z); Bs[nb][lc+3][lr]=f2tf(b0.w);
            Bs[nb][lc+8][lr]=f2tf(b1.x); Bs[nb][lc+9][lr]=f2tf(b1.y); Bs[nb][lc+10][lr]=f2tf(b1.z); Bs[nb][lc+11][lr]=f2tf(b1.w);
            __syncthreads();
            cur = nb;
        }
    }

    #pragma unroll
    for (int mt = 0; mt < 4; mt++) {
        #pragma unroll
        for (int nt = 0; nt < 4; nt++) {
            int m = m0 + wm + mt*16 + r;
            int n = n0 + wn + nt*8 + 2*q;
            float* a4 = acc[mt][nt];
            float bv0 = bias[n], bv1 = bias[n+1];
            if (EPI == 0) {
                *(float2*)&out[(size_t)m*DMdim + n]     = make_float2(a4[0]+bv0, a4[1]+bv1);
                *(float2*)&out[(size_t)(m+8)*DMdim + n] = make_float2(a4[2]+bv0, a4[3]+bv1);
            } else {
                int bb = m >> 11, s = m & 2047, h = n >> 6, d = n & 63;
                size_t base = ((size_t)(bb*Hdim + h)) * Sdim;
                *(float2*)&out[(base + s)*DPT + d]     = make_float2(a4[0]+bv0, a4[1]+bv1);
                *(float2*)&out[(base + s + 8)*DPT + d] = make_float2(a4[2]+bv0, a4[3]+bv1);
            }
        }
    }
}

// ---------------------------------------------------------------------------
// QK^T (tf32) + fused exp (R7 version): P = exp(Q@K^T * 0.125 + mask*(-1e9))
// Writes unnormalized P to attn and per-(row, col-tile) sums to g_psum.
// ---------------------------------------------------------------------------
__global__ void __launch_bounds__(256, 2)
qk_tf32(const float* __restrict__ mask, float* __restrict__ attn, int bh_base)
{
    const int K = DPT;
    __shared__ uint32_t As[16][136];
    __shared__ uint32_t Bs[16][136];
    __shared__ float sred[128][4];
    int t = threadIdx.x, lane = t & 31, w = t >> 5;
    int q = lane & 3, r = lane >> 2;
    int zl = blockIdx.z, bh = bh_base + zl;
    int m0 = blockIdx.y * 128, n0 = blockIdx.x * 128;
    int wm = (w & 1) * 64, wn = (w >> 1) * 32;
    int wnidx = w >> 1;
    int lr = t >> 1, lc = (t & 1) * 4;
    const float* Q  = g_qh + (size_t)bh * Sdim * DPT;
    const float* Kh = g_kh + (size_t)bh * Sdim * DPT;
    const float* Ap = Q  + (size_t)(m0 + lr) * K + lc;
    const float* Wp = Kh + (size_t)(n0 + lr) * K + lc;

    float acc[4][4][4];
    #pragma unroll
    for (int i = 0; i < 4; i++)
        #pragma unroll
        for (int j = 0; j < 4; j++)
            #pragma unroll
            for (int v = 0; v < 4; v++) acc[i][j][v] = 0.f;

    float4 pa0 = *(const float4*)Ap, pa1 = *(const float4*)(Ap + 8);
    float4 pb0 = *(const float4*)Wp, pb1 = *(const float4*)(Wp + 8);

    #pragma unroll
    for (int kt = 0; kt < K; kt += 16) {
        __syncthreads();
        As[lc+0][lr]=f2tf(pa0.x); As[lc+1][lr]=f2tf(pa0.y); As[lc+2][lr]=f2tf(pa0.z); As[lc+3][lr]=f2tf(pa0.w);
        As[lc+8][lr]=f2tf(pa1.x); As[lc+9][lr]=f2tf(pa1.y); As[lc+10][lr]=f2tf(pa1.z); As[lc+11][lr]=f2tf(pa1.w);
        Bs[lc+0][lr]=f2tf(pb0.x); Bs[lc+1][lr]=f2tf(pb0.y); Bs[lc+2][lr]=f2tf(pb0.z); Bs[lc+3][lr]=f2tf(pb0.w);
        Bs[lc+8][lr]=f2tf(pb1.x); Bs[lc+9][lr]=f2tf(pb1.y); Bs[lc+10][lr]=f2tf(pb1.z); Bs[lc+11][lr]=f2tf(pb1.w);
        __syncthreads();
        if (kt + 16 < K) {
            pa0 = *(const float4*)(Ap + kt + 16); pa1 = *(const float4*)(Ap + kt + 24);
            pb0 = *(const float4*)(Wp + kt + 16); pb1 = *(const float4*)(Wp + kt + 24);
        }
        #pragma unroll
        for (int ks = 0; ks < 2; ks++) {
            uint32_t af[4][4], bf[4][2];
            #pragma unroll
            for (int mt = 0; mt < 4; mt++) {
                af[mt][0] = As[ks*8 + q][wm + mt*16 + r];
                af[mt][1] = As[ks*8 + q][wm + mt*16 + 8 + r];
                af[mt][2] = As[ks*8 + 4 + q][wm + mt*16 + r];
                af[mt][3] = As[ks*8 + 4 + q][wm + mt*16 + 8 + r];
            }
            #pragma unroll
            for (int nt = 0; nt < 4; nt++) {
                bf[nt][0] = Bs[ks*8 + q][wn + nt*8 + r];
                bf[nt][1] = Bs[ks*8 + 4 + q][wn + nt*8 + r];
            }
            #pragma unroll
            for (int mt = 0; mt < 4; mt++)
                #pragma unroll
                for (int nt = 0; nt < 4; nt++)
                    mma8(acc[mt][nt], af[mt], bf[nt]);
        }
    }

    const float* mrow = mask + (size_t)(bh >> 4) * Sdim;
    float* orow = attn + (size_t)zl * Sdim * Sdim;
    float rsum[8];
    #pragma unroll
    for (int i = 0; i < 8; i++) rsum[i] = 0.f;

    #pragma unroll
    for (int mt = 0; mt < 4; mt++) {
        #pragma unroll
        for (int nt = 0; nt < 4; nt++) {
            int m = m0 + wm + mt*16 + r;
            int n = n0 + wn + nt*8 + 2*q;
            float* a4 = acc[mt][nt];
            float mk0 = mrow[n] * (-1e9f), mk1 = mrow[n+1] * (-1e9f);
            float p0 = __expf(a4[0]*0.125f + mk0);
            float p1 = __expf(a4[1]*0.125f + mk1);
            float p2 = __expf(a4[2]*0.125f + mk0);
            float p3 = __expf(a4[3]*0.125f + mk1);
            *(float2*)&orow[(size_t)m*Sdim + n]     = make_float2(p0, p1);
            *(float2*)&orow[(size_t)(m+8)*Sdim + n] = make_float2(p2, p3);
            rsum[mt*2+0] += p0 + p1;
            rsum[mt*2+1] += p2 + p3;
        }
    }
    #pragma unroll
    for (int i = 0; i < 8; i++) {
        rsum[i] += __shfl_xor_sync(0xffffffffu, rsum[i], 1);
        rsum[i] += __shfl_xor_sync(0xffffffffu, rsum[i], 2);
    }
    if (q == 0) {
        #pragma unroll
        for (int mt = 0; mt < 4; mt++) {
            sred[wm + mt*16 + r][wnidx]     = rsum[mt*2+0];
            sred[wm + mt*16 + 8 + r][wnidx] = rsum[mt*2+1];
        }
    }
    __syncthreads();
    if (t < 128) {
        float s = sred[t][0] + sred[t][1] + sred[t][2] + sred[t][3];
        g_psum[((size_t)bh * Sdim + m0 + t) * NCTILE + blockIdx.x] = s;
    }
}

// ---------------------------------------------------------------------------
// PV (tf32) + fused normalize (R7 version): inv = 1/rowsum; normalized P
// written back to attn in place; ctx = Pn @ V into g_concat.
// ---------------------------------------------------------------------------
__global__ void __launch_bounds__(256, 2)
pv_tf32(float* __restrict__ attn, int bh_base)
{
    __shared__ uint32_t Ps[32][136];   // [k][m]
    __shared__ uint32_t Vs[32][72];    // [k][n]
    __shared__ float sinv[128];
    int t = threadIdx.x, lane = t & 31, w = t >> 5;
    int q = lane & 3, r = lane >> 2;
    int zl = blockIdx.y, bh = bh_base + zl;
    int m0 = blockIdx.x * 128;
    int wm = (w & 3) * 32, wn = (w >> 2) * 32;
    float* P = attn + (size_t)zl * Sdim * Sdim;
    const float* V = g_vh + (size_t)bh * Sdim * DPT;

    if (t < 128) {
        const float* pp = &g_psum[((size_t)bh * Sdim + m0 + t) * NCTILE];
        float s = 0.f;
        #pragma unroll
        for (int i = 0; i < NCTILE; i++) s += pp[i];
        sinv[t] = 1.0f / s;
    }
    __syncthreads();

    int lr = t >> 1, lc = (t & 1) * 16;
    float* Pp = P + (size_t)(m0 + lr) * Sdim + lc;
    int vr = t >> 3, vc = (t & 7) * 8;
    const float* Vp = V + (size_t)vr * DPT + vc;
    float inv_r = sinv[lr];

    float acc[2][4][4];
    #pragma unroll
    for (int i = 0; i < 2; i++)
        #pragma unroll
        for (int j = 0; j < 4; j++)
            #pragma unroll
            for (int v = 0; v < 4; v++) acc[i][j][v] = 0.f;

    float4 pa[4];
    #pragma unroll
    for (int i = 0; i < 4; i++) pa[i] = *(const float4*)(Pp + 4*i);
    float4 pv0 = *(const float4*)(Vp);
    float4 pv1 = *(const float4*)(Vp + 4);

    for (int kt = 0; kt < Sdim; kt += 32) {
        float4 sa[4];
        #pragma unroll
        for (int i = 0; i < 4; i++) {
            sa[i].x = pa[i].x * inv_r; sa[i].y = pa[i].y * inv_r;
            sa[i].z = pa[i].z * inv_r; sa[i].w = pa[i].w * inv_r;
        }
        #pragma unroll
        for (int i = 0; i < 4; i++)
            *(float4*)(Pp + kt + 4*i) = sa[i];

        __syncthreads();
        #pragma unroll
        for (int i = 0; i < 4; i++) {
            int kk = lc + 4*i;
            Ps[kk+0][lr] = f2tf(sa[i].x); Ps[kk+1][lr] = f2tf(sa[i].y);
            Ps[kk+2][lr] = f2tf(sa[i].z); Ps[kk+3][lr] = f2tf(sa[i].w);
        }
        Vs[vr][vc+0] = f2tf(pv0.x); Vs[vr][vc+1] = f2tf(pv0.y);
        Vs[vr][vc+2] = f2tf(pv0.z); Vs[vr][vc+3] = f2tf(pv0.w);
        Vs[vr][vc+4] = f2tf(pv1.x); Vs[vr][vc+5] = f2tf(pv1.y);
        Vs[vr][vc+6] = f2tf(pv1.z); Vs[vr][vc+7] = f2tf(pv1.w);
        __syncthreads();
        if (kt + 32 < Sdim) {
            #pragma unroll
            for (int i = 0; i < 4; i++) pa[i] = *(const float4*)(Pp + kt + 32 + 4*i);
            pv0 = *(const float4*)(Vp + (size_t)(kt + 32) * DPT);
            pv1 = *(const float4*)(Vp + (size_t)(kt + 32) * DPT + 4);
        }
        #pragma unroll
        for (int ks = 0; ks < 4; ks++) {
            uint32_t af[2][4], bf[4][2];
            #pragma unroll
            for (int mt = 0; mt < 2; mt++) {
                af[mt][0] = Ps[ks*8 + q][wm + mt*16 + r];
                af[mt][1] = Ps[ks*8 + q][wm + mt*16 + 8 + r];
                af[mt][2] = Ps[ks*8 + 4 + q][wm + mt*16 + r];
                af[mt][3] = Ps[ks*8 + 4 + q][wm + mt*16 + 8 + r];
            }
            #pragma unroll
            for (int nt = 0; nt < 4; nt++) {
                bf[nt][0] = Vs[ks*8 + q][wn + nt*8 + r];
                bf[nt][1] = Vs[ks*8 + 4 + q][wn + nt*8 + r];
            }
            #pragma unroll
            for (int mt = 0; mt < 2; mt++)
                #pragma unroll
                for (int nt = 0; nt < 4; nt++)
                    mma8(acc[mt][nt], af[mt], bf[nt]);
        }
    }

    int bb = bh >> 4, h = bh & 15;
    #pragma unroll
    for (int mt = 0; mt < 2; mt++) {
        #pragma unroll
        for (int nt = 0; nt < 4; nt++) {
            int s = m0 + wm + mt*16 + r;
            int dcol = wn + nt*8 + 2*q;
            float* a4 = acc[mt][nt];
            size_t base = ((size_t)bb * Sdim + s) * DMdim + h*DPT + dcol;
            *(float2*)&g_concat[base]            = make_float2(a4[0], a4[1]);
            *(float2*)&g_concat[base + 8*DMdim]  = make_float2(a4[2], a4[3]);
        }
    }
}

// ---------------------------------------------------------------------------
extern "C" void kernel_launch(void* const* d_in, const int* in_sizes, int n_in,
                              void* d_out, int out_size)
{
    const float* v_in    = (const float*)d_in[0];
    const float* k_in    = (const float*)d_in[1];
    const float* q_in    = (const float*)d_in[2];
    const float* mask    = (const float*)d_in[3];
    const float* wq_w    = (const float*)d_in[4];
    const float* wq_b    = (const float*)d_in[5];
    const float* wk_w    = (const float*)d_in[6];
    const float* wk_b    = (const float*)d_in[7];
    const float* wv_w    = (const float*)d_in[8];
    const float* wv_b    = (const float*)d_in[9];
    const float* dense_w = (const float*)d_in[10];
    const float* dense_b = (const float*)d_in[11];

    float *qh, *kh, *vh, *concat, *attn_chunk;
    cudaGetSymbolAddress((void**)&qh, g_qh);
    cudaGetSymbolAddress((void**)&kh, g_kh);
    cudaGetSymbolAddress((void**)&vh, g_vh);
    cudaGetSymbolAddress((void**)&concat, g_concat);
    cudaGetSymbolAddress((void**)&attn_chunk, g_attn_chunk);

    float* out = (float*)d_out;
    int attn_in_out = ((long long)out_size >= (long long)OUT_ELEMS + ATTN_ELEMS);

    dim3 blk(256);
    dim3 g_gemm(DMdim / 128, (Bdim * Sdim) / 128);   // (8, 64)

    gemm1024_tf32<1><<<g_gemm, blk>>>(q_in, wq_w, wq_b, qh);
    gemm1024_tf32<1><<<g_gemm, blk>>>(k_in, wk_w, wk_b, kh);
    gemm1024_tf32<1><<<g_gemm, blk>>>(v_in, wv_w, wv_b, vh);

    if (attn_in_out) {
        float* attn = out + OUT_ELEMS;
        qk_tf32<<<dim3(NCTILE, Sdim/128, BHdim), blk>>>(mask, attn, 0);
        pv_tf32<<<dim3(Sdim/128, BHdim), blk>>>(attn, 0);
    } else {
        for (int c = 0; c < BHdim; c += CHUNK_BH) {
            qk_tf32<<<dim3(NCTILE, Sdim/128, CHUNK_BH), blk>>>(mask, attn_chunk, c);
            pv_tf32<<<dim3(Sdim/128, CHUNK_BH), blk>>>(attn_chunk, c);
        }
    }

    gemm1024_tf32<0><<<g_gemm, blk>>>(concat, dense_w, dense_b, out);
}

// round 14
// speedup vs baseline: 1.1244x; 1.0020x over previous
#include <cuda_runtime.h>
#include <math.h>
#include <stdint.h>

// Problem dims
#define Bdim   4
#define Sdim   2048
#define DMdim  1024
#define Hdim   16
#define DPT    64
#define BHdim  (Bdim*Hdim)

#define OUT_ELEMS  (Bdim*Sdim*DMdim)                 // 8388608
#define ATTN_ELEMS ((long long)BHdim*Sdim*Sdim)      // 268435456
#define CHUNK_BH   4
#define NCTILE     16                                 // Sdim/128 col tiles

// Scratch (allocation-free: __device__ globals). ~206 MB total.
__device__ float g_qh[(size_t)BHdim*Sdim*DPT];
__device__ float g_kh[(size_t)BHdim*Sdim*DPT];
__device__ float g_vh[(size_t)BHdim*Sdim*DPT];
__device__ float g_concat[(size_t)Bdim*Sdim*DMdim];
__device__ float g_psum[(size_t)BHdim*Sdim*NCTILE];  // per-(row, col-tile) exp sums
__device__ float g_attn_chunk[(size_t)CHUNK_BH*Sdim*Sdim];

// ---------------------------------------------------------------------------
__device__ __forceinline__ uint32_t f2tf(float x) {
    uint32_t r;
    asm("cvt.rna.tf32.f32 %0, %1;" : "=r"(r) : "f"(x));
    return r;
}

__device__ __forceinline__ void mma8(float* c, const uint32_t* a, const uint32_t* b) {
    asm volatile(
        "mma.sync.aligned.m16n8k8.row.col.f32.tf32.tf32.f32 "
        "{%0,%1,%2,%3},{%4,%5,%6,%7},{%8,%9},{%0,%1,%2,%3};\n"
        : "+f"(c[0]), "+f"(c[1]), "+f"(c[2]), "+f"(c[3])
        : "r"(a[0]), "r"(a[1]), "r"(a[2]), "r"(a[3]), "r"(b[0]), "r"(b[1]));
}

// ---------------------------------------------------------------------------
// tf32 GEMM: C(128x128/block) = A(MxK) @ W(NxK)^T (+bias), K=1024, BK=16
// DOUBLE-BUFFERED smem: one __syncthreads per k-iteration. (R10 verified)
// EPI: 0 = dense row-major (M x DMdim), 1 = head-scatter to (B,H,S,DPT)
// ---------------------------------------------------------------------------
template<int EPI>
__global__ void __launch_bounds__(256, 2)
gemm1024_tf32(const float* __restrict__ A, const float* __restrict__ W,
              const float* __restrict__ bias, float* __restrict__ out)
{
    const int K = 1024;
    __shared__ uint32_t As[2][16][136];
    __shared__ uint32_t Bs[2][16][136];
    int t = threadIdx.x, lane = t & 31, w = t >> 5;
    int q = lane & 3, r = lane >> 2;
    int m0 = blockIdx.y * 128, n0 = blockIdx.x * 128;
    int wm = (w & 1) * 64, wn = (w >> 1) * 32;
    int lr = t >> 1, lc = (t & 1) * 4;
    const float* Ap = A + (size_t)(m0 + lr) * K + lc;
    const float* Wp = W + (size_t)(n0 + lr) * K + lc;

    float acc[4][4][4];
    #pragma unroll
    for (int i = 0; i < 4; i++)
        #pragma unroll
        for (int j = 0; j < 4; j++)
            #pragma unroll
            for (int v = 0; v < 4; v++) acc[i][j][v] = 0.f;

    {
        float4 a0 = *(const float4*)Ap,  a1 = *(const float4*)(Ap + 8);
        float4 b0 = *(const float4*)Wp,  b1 = *(const float4*)(Wp + 8);
        As[0][lc+0][lr]=f2tf(a0.x); As[0][lc+1][lr]=f2tf(a0.y); As[0][lc+2][lr]=f2tf(a0.z); As[0][lc+3][lr]=f2tf(a0.w);
        As[0][lc+8][lr]=f2tf(a1.x); As[0][lc+9][lr]=f2tf(a1.y); As[0][lc+10][lr]=f2tf(a1.z); As[0][lc+11][lr]=f2tf(a1.w);
        Bs[0][lc+0][lr]=f2tf(b0.x); Bs[0][lc+1][lr]=f2tf(b0.y); Bs[0][lc+2][lr]=f2tf(b0.z); Bs[0][lc+3][lr]=f2tf(b0.w);
        Bs[0][lc+8][lr]=f2tf(b1.x); Bs[0][lc+9][lr]=f2tf(b1.y); Bs[0][lc+10][lr]=f2tf(b1.z); Bs[0][lc+11][lr]=f2tf(b1.w);
    }
    __syncthreads();

    int cur = 0;
    for (int kt = 0; kt < K; kt += 16) {
        float4 a0, a1, b0, b1;
        bool nxt = (kt + 16 < K);
        if (nxt) {
            a0 = *(const float4*)(Ap + kt + 16); a1 = *(const float4*)(Ap + kt + 24);
            b0 = *(const float4*)(Wp + kt + 16); b1 = *(const float4*)(Wp + kt + 24);
        }
        #pragma unroll
        for (int ks = 0; ks < 2; ks++) {
            uint32_t af[4][4], bf[4][2];
            #pragma unroll
            for (int mt = 0; mt < 4; mt++) {
                af[mt][0] = As[cur][ks*8 + q][wm + mt*16 + r];
                af[mt][1] = As[cur][ks*8 + q][wm + mt*16 + 8 + r];
                af[mt][2] = As[cur][ks*8 + 4 + q][wm + mt*16 + r];
                af[mt][3] = As[cur][ks*8 + 4 + q][wm + mt*16 + 8 + r];
            }
            #pragma unroll
            for (int nt = 0; nt < 4; nt++) {
                bf[nt][0] = Bs[cur][ks*8 + q][wn + nt*8 + r];
                bf[nt][1] = Bs[cur][ks*8 + 4 + q][wn + nt*8 + r];
            }
            #pragma unroll
            for (int mt = 0; mt < 4; mt++)
                #pragma unroll
                for (int nt = 0; nt < 4; nt++)
                    mma8(acc[mt][nt], af[mt], bf[nt]);
        }
        if (nxt) {
            int nb = cur ^ 1;
            As[nb][lc+0][lr]=f2tf(a0.x); As[nb][lc+1][lr]=f2tf(a0.y); As[nb][lc+2][lr]=f2tf(a0.z); As[nb][lc+3][lr]=f2tf(a0.w);
            As[nb][lc+8][lr]=f2tf(a1.x); As[nb][lc+9][lr]=f2tf(a1.y); As[nb][lc+10][lr]=f2tf(a1.z); As[nb][lc+11][lr]=f2tf(a1.w);
            Bs[nb][lc+0][lr]=f2tf(b0.x); Bs[nb][lc+1][lr]=f2tf(b0.y); Bs[nb][lc+2][lr]=f2tf(b0.z); Bs[nb][lc+3][lr]=f2tf(b0.w);
            Bs[nb][lc+8][lr]=f2tf(b1.x); Bs[nb][lc+9][lr]=f2tf(b1.y); Bs[nb][lc+10][lr]=f2tf(b1.z); Bs[nb][lc+11][lr]=f2tf(b1.w);
            __syncthreads();
            cur = nb;
        }
    }

    #pragma unroll
    for (int mt = 0; mt < 4; mt++) {
        #pragma unroll
        for (int nt = 0; nt < 4; nt++) {
            int m = m0 + wm + mt*16 + r;
            int n = n0 + wn + nt*8 + 2*q;
            float* a4 = acc[mt][nt];
            float bv0 = bias[n], bv1 = bias[n+1];
            if (EPI == 0) {
                *(float2*)&out[(size_t)m*DMdim + n]     = make_float2(a4[0]+bv0, a4[1]+bv1);
                *(float2*)&out[(size_t)(m+8)*DMdim + n] = make_float2(a4[2]+bv0, a4[3]+bv1);
            } else {
                int bb = m >> 11, s = m & 2047, h = n >> 6, d = n & 63;
                size_t base = ((size_t)(bb*Hdim + h)) * Sdim;
                *(float2*)&out[(base + s)*DPT + d]     = make_float2(a4[0]+bv0, a4[1]+bv1);
                *(float2*)&out[(base + s + 8)*DPT + d] = make_float2(a4[2]+bv0, a4[3]+bv1);
            }
        }
    }
}

// ---------------------------------------------------------------------------
// QK^T (tf32) + fused exp (unchanged R10): P = exp(Q@K^T*0.125 + mask*(-1e9))
// ---------------------------------------------------------------------------
__global__ void __launch_bounds__(256, 2)
qk_tf32(const float* __restrict__ mask, float* __restrict__ attn, int bh_base)
{
    const int K = DPT;
    __shared__ uint32_t As[16][136];
    __shared__ uint32_t Bs[16][136];
    __shared__ float sred[128][4];
    int t = threadIdx.x, lane = t & 31, w = t >> 5;
    int q = lane & 3, r = lane >> 2;
    int zl = blockIdx.z, bh = bh_base + zl;
    int m0 = blockIdx.y * 128, n0 = blockIdx.x * 128;
    int wm = (w & 1) * 64, wn = (w >> 1) * 32;
    int wnidx = w >> 1;
    int lr = t >> 1, lc = (t & 1) * 4;
    const float* Q  = g_qh + (size_t)bh * Sdim * DPT;
    const float* Kh = g_kh + (size_t)bh * Sdim * DPT;
    const float* Ap = Q  + (size_t)(m0 + lr) * K + lc;
    const float* Wp = Kh + (size_t)(n0 + lr) * K + lc;

    float acc[4][4][4];
    #pragma unroll
    for (int i = 0; i < 4; i++)
        #pragma unroll
        for (int j = 0; j < 4; j++)
            #pragma unroll
            for (int v = 0; v < 4; v++) acc[i][j][v] = 0.f;

    float4 pa0 = *(const float4*)Ap, pa1 = *(const float4*)(Ap + 8);
    float4 pb0 = *(const float4*)Wp, pb1 = *(const float4*)(Wp + 8);

    #pragma unroll
    for (int kt = 0; kt < K; kt += 16) {
        __syncthreads();
        As[lc+0][lr]=f2tf(pa0.x); As[lc+1][lr]=f2tf(pa0.y); As[lc+2][lr]=f2tf(pa0.z); As[lc+3][lr]=f2tf(pa0.w);
        As[lc+8][lr]=f2tf(pa1.x); As[lc+9][lr]=f2tf(pa1.y); As[lc+10][lr]=f2tf(pa1.z); As[lc+11][lr]=f2tf(pa1.w);
        Bs[lc+0][lr]=f2tf(pb0.x); Bs[lc+1][lr]=f2tf(pb0.y); Bs[lc+2][lr]=f2tf(pb0.z); Bs[lc+3][lr]=f2tf(pb0.w);
        Bs[lc+8][lr]=f2tf(pb1.x); Bs[lc+9][lr]=f2tf(pb1.y); Bs[lc+10][lr]=f2tf(pb1.z); Bs[lc+11][lr]=f2tf(pb1.w);
        __syncthreads();
        if (kt + 16 < K) {
            pa0 = *(const float4*)(Ap + kt + 16); pa1 = *(const float4*)(Ap + kt + 24);
            pb0 = *(const float4*)(Wp + kt + 16); pb1 = *(const float4*)(Wp + kt + 24);
        }
        #pragma unroll
        for (int ks = 0; ks < 2; ks++) {
            uint32_t af[4][4], bf[4][2];
            #pragma unroll
            for (int mt = 0; mt < 4; mt++) {
                af[mt][0] = As[ks*8 + q][wm + mt*16 + r];
                af[mt][1] = As[ks*8 + q][wm + mt*16 + 8 + r];
                af[mt][2] = As[ks*8 + 4 + q][wm + mt*16 + r];
                af[mt][3] = As[ks*8 + 4 + q][wm + mt*16 + 8 + r];
            }
            #pragma unroll
            for (int nt = 0; nt < 4; nt++) {
                bf[nt][0] = Bs[ks*8 + q][wn + nt*8 + r];
                bf[nt][1] = Bs[ks*8 + 4 + q][wn + nt*8 + r];
            }
            #pragma unroll
            for (int mt = 0; mt < 4; mt++)
                #pragma unroll
                for (int nt = 0; nt < 4; nt++)
                    mma8(acc[mt][nt], af[mt], bf[nt]);
        }
    }

    const float* mrow = mask + (size_t)(bh >> 4) * Sdim;
    float* orow = attn + (size_t)zl * Sdim * Sdim;
    float rsum[8];
    #pragma unroll
    for (int i = 0; i < 8; i++) rsum[i] = 0.f;

    #pragma unroll
    for (int mt = 0; mt < 4; mt++) {
        #pragma unroll
        for (int nt = 0; nt < 4; nt++) {
            int m = m0 + wm + mt*16 + r;
            int n = n0 + wn + nt*8 + 2*q;
            float* a4 = acc[mt][nt];
            float mk0 = mrow[n] * (-1e9f), mk1 = mrow[n+1] * (-1e9f);
            float p0 = __expf(a4[0]*0.125f + mk0);
            float p1 = __expf(a4[1]*0.125f + mk1);
            float p2 = __expf(a4[2]*0.125f + mk0);
            float p3 = __expf(a4[3]*0.125f + mk1);
            *(float2*)&orow[(size_t)m*Sdim + n]     = make_float2(p0, p1);
            *(float2*)&orow[(size_t)(m+8)*Sdim + n] = make_float2(p2, p3);
            rsum[mt*2+0] += p0 + p1;
            rsum[mt*2+1] += p2 + p3;
        }
    }
    #pragma unroll
    for (int i = 0; i < 8; i++) {
        rsum[i] += __shfl_xor_sync(0xffffffffu, rsum[i], 1);
        rsum[i] += __shfl_xor_sync(0xffffffffu, rsum[i], 2);
    }
    if (q == 0) {
        #pragma unroll
        for (int mt = 0; mt < 4; mt++) {
            sred[wm + mt*16 + r][wnidx]     = rsum[mt*2+0];
            sred[wm + mt*16 + 8 + r][wnidx] = rsum[mt*2+1];
        }
    }
    __syncthreads();
    if (t < 128) {
        float s = sred[t][0] + sred[t][1] + sred[t][2] + sred[t][3];
        g_psum[((size_t)bh * Sdim + m0 + t) * NCTILE + blockIdx.x] = s;
    }
}

// ---------------------------------------------------------------------------
// PV (tf32) + fused normalize, DOUBLE-BUFFERED (one sync per 32-k iteration).
// Dynamic smem: Ps[2][32][136] + Vs[2][32][72] = 52 KB; 2 CTAs/SM.
// Normalized P written back to attn in place; ctx = Pn @ V into g_concat.
// ---------------------------------------------------------------------------
#define PV_SM_BYTES (2*32*136*4 + 2*32*72*4)   // 53248

__global__ void __launch_bounds__(256, 2)
pv_tf32(float* __restrict__ attn, int bh_base)
{
    extern __shared__ uint32_t pvsm[];
    uint32_t* PsBuf = pvsm;                 // [2][32][136]
    uint32_t* VsBuf = pvsm + 2*32*136;      // [2][32][72]
    #define PSX(b,k,m) PsBuf[(b)*4352 + (k)*136 + (m)]
    #define VSX(b,k,n) VsBuf[(b)*2304 + (k)*72 + (n)]
    __shared__ float sinv[128];

    int t = threadIdx.x, lane = t & 31, w = t >> 5;
    int q = lane & 3, r = lane >> 2;
    int zl = blockIdx.y, bh = bh_base + zl;
    int m0 = blockIdx.x * 128;
    int wm = (w & 3) * 32, wn = (w >> 2) * 32;
    float* P = attn + (size_t)zl * Sdim * Sdim;
    const float* V = g_vh + (size_t)bh * Sdim * DPT;

    if (t < 128) {
        const float* pp = &g_psum[((size_t)bh * Sdim + m0 + t) * NCTILE];
        float s = 0.f;
        #pragma unroll
        for (int i = 0; i < NCTILE; i++) s += pp[i];
        sinv[t] = 1.0f / s;
    }
    __syncthreads();

    int lr = t >> 1, lc = (t & 1) * 16;
    float* Pp = P + (size_t)(m0 + lr) * Sdim + lc;
    int vr = t >> 3, vc = (t & 7) * 8;
    const float* Vp = V + (size_t)vr * DPT + vc;
    float inv_r = sinv[lr];

    float acc[2][4][4];
    #pragma unroll
    for (int i = 0; i < 2; i++)
        #pragma unroll
        for (int j = 0; j < 4; j++)
            #pragma unroll
            for (int v = 0; v < 4; v++) acc[i][j][v] = 0.f;

    // prologue: chunk 0 -> buffer 0 (normalize + write-back + stage)
    {
        float4 pa[4];
        #pragma unroll
        for (int i = 0; i < 4; i++) pa[i] = *(const float4*)(Pp + 4*i);
        float4 v0 = *(const float4*)(Vp);
        float4 v1 = *(const float4*)(Vp + 4);
        #pragma unroll
        for (int i = 0; i < 4; i++) {
            float4 sa = make_float4(pa[i].x*inv_r, pa[i].y*inv_r, pa[i].z*inv_r, pa[i].w*inv_r);
            *(float4*)(Pp + 4*i) = sa;
            int kk = lc + 4*i;
            PSX(0, kk+0, lr) = f2tf(sa.x); PSX(0, kk+1, lr) = f2tf(sa.y);
            PSX(0, kk+2, lr) = f2tf(sa.z); PSX(0, kk+3, lr) = f2tf(sa.w);
        }
        VSX(0, vr, vc+0) = f2tf(v0.x); VSX(0, vr, vc+1) = f2tf(v0.y);
        VSX(0, vr, vc+2) = f2tf(v0.z); VSX(0, vr, vc+3) = f2tf(v0.w);
        VSX(0, vr, vc+4) = f2tf(v1.x); VSX(0, vr, vc+5) = f2tf(v1.y);
        VSX(0, vr, vc+6) = f2tf(v1.z); VSX(0, vr, vc+7) = f2tf(v1.w);
    }
    __syncthreads();

    int cur = 0;
    for (int kt = 0; kt < Sdim; kt += 32) {
        bool nxt = (kt + 32 < Sdim);
        float4 npa[4], nv0, nv1;
        if (nxt) {
            #pragma unroll
            for (int i = 0; i < 4; i++) npa[i] = *(const float4*)(Pp + kt + 32 + 4*i);
            nv0 = *(const float4*)(Vp + (size_t)(kt + 32) * DPT);
            nv1 = *(const float4*)(Vp + (size_t)(kt + 32) * DPT + 4);
        }
        // MMA on buffer cur
        #pragma unroll
        for (int ks = 0; ks < 4; ks++) {
            uint32_t af[2][4], bf[4][2];
            #pragma unroll
            for (int mt = 0; mt < 2; mt++) {
                af[mt][0] = PSX(cur, ks*8 + q,     wm + mt*16 + r);
                af[mt][1] = PSX(cur, ks*8 + q,     wm + mt*16 + 8 + r);
                af[mt][2] = PSX(cur, ks*8 + 4 + q, wm + mt*16 + r);
                af[mt][3] = PSX(cur, ks*8 + 4 + q, wm + mt*16 + 8 + r);
            }
            #pragma unroll
            for (int nt = 0; nt < 4; nt++) {
                bf[nt][0] = VSX(cur, ks*8 + q,     wn + nt*8 + r);
                bf[nt][1] = VSX(cur, ks*8 + 4 + q, wn + nt*8 + r);
            }
            #pragma unroll
            for (int mt = 0; mt < 2; mt++)
                #pragma unroll
                for (int nt = 0; nt < 4; nt++)
                    mma8(acc[mt][nt], af[mt], bf[nt]);
        }
        if (nxt) {
            int nb = cur ^ 1;
            #pragma unroll
            for (int i = 0; i < 4; i++) {
                float4 sa = make_float4(npa[i].x*inv_r, npa[i].y*inv_r, npa[i].z*inv_r, npa[i].w*inv_r);
                *(float4*)(Pp + kt + 32 + 4*i) = sa;
                int kk = lc + 4*i;
                PSX(nb, kk+0, lr) = f2tf(sa.x); PSX(nb, kk+1, lr) = f2tf(sa.y);
                PSX(nb, kk+2, lr) = f2tf(sa.z); PSX(nb, kk+3, lr) = f2tf(sa.w);
            }
            VSX(nb, vr, vc+0) = f2tf(nv0.x); VSX(nb, vr, vc+1) = f2tf(nv0.y);
            VSX(nb, vr, vc+2) = f2tf(nv0.z); VSX(nb, vr, vc+3) = f2tf(nv0.w);
            VSX(nb, vr, vc+4) = f2tf(nv1.x); VSX(nb, vr, vc+5) = f2tf(nv1.y);
            VSX(nb, vr, vc+6) = f2tf(nv1.z); VSX(nb, vr, vc+7) = f2tf(nv1.w);
            __syncthreads();
            cur = nb;
        }
    }

    int bb = bh >> 4, h = bh & 15;
    #pragma unroll
    for (int mt = 0; mt < 2; mt++) {
        #pragma unroll
        for (int nt = 0; nt < 4; nt++) {
            int s = m0 + wm + mt*16 + r;
            int dcol = wn + nt*8 + 2*q;
            float* a4 = acc[mt][nt];
            size_t base = ((size_t)bb * Sdim + s) * DMdim + h*DPT + dcol;
            *(float2*)&g_concat[base]            = make_float2(a4[0], a4[1]);
            *(float2*)&g_concat[base + 8*DMdim]  = make_float2(a4[2], a4[3]);
        }
    }
}

// ---------------------------------------------------------------------------
extern "C" void kernel_launch(void* const* d_in, const int* in_sizes, int n_in,
                              void* d_out, int out_size)
{
    const float* v_in    = (const float*)d_in[0];
    const float* k_in    = (const float*)d_in[1];
    const float* q_in    = (const float*)d_in[2];
    const float* mask    = (const float*)d_in[3];
    const float* wq_w    = (const float*)d_in[4];
    const float* wq_b    = (const float*)d_in[5];
    const float* wk_w    = (const float*)d_in[6];
    const float* wk_b    = (const float*)d_in[7];
    const float* wv_w    = (const float*)d_in[8];
    const float* wv_b    = (const float*)d_in[9];
    const float* dense_w = (const float*)d_in[10];
    const float* dense_b = (const float*)d_in[11];

    float *qh, *kh, *vh, *concat, *attn_chunk;
    cudaGetSymbolAddress((void**)&qh, g_qh);
    cudaGetSymbolAddress((void**)&kh, g_kh);
    cudaGetSymbolAddress((void**)&vh, g_vh);
    cudaGetSymbolAddress((void**)&concat, g_concat);
    cudaGetSymbolAddress((void**)&attn_chunk, g_attn_chunk);

    float* out = (float*)d_out;
    int attn_in_out = ((long long)out_size >= (long long)OUT_ELEMS + ATTN_ELEMS);

    cudaFuncSetAttribute(pv_tf32, cudaFuncAttributeMaxDynamicSharedMemorySize, PV_SM_BYTES);

    dim3 blk(256);
    dim3 g_gemm(DMdim / 128, (Bdim * Sdim) / 128);   // (8, 64)

    gemm1024_tf32<1><<<g_gemm, blk>>>(q_in, wq_w, wq_b, qh);
    gemm1024_tf32<1><<<g_gemm, blk>>>(k_in, wk_w, wk_b, kh);
    gemm1024_tf32<1><<<g_gemm, blk>>>(v_in, wv_w, wv_b, vh);

    if (attn_in_out) {
        float* attn = out + OUT_ELEMS;
        qk_tf32<<<dim3(NCTILE, Sdim/128, BHdim), blk>>>(mask, attn, 0);
        pv_tf32<<<dim3(Sdim/128, BHdim), blk, PV_SM_BYTES>>>(attn, 0);
    } else {
        for (int c = 0; c < BHdim; c += CHUNK_BH) {
            qk_tf32<<<dim3(NCTILE, Sdim/128, CHUNK_BH), blk>>>(mask, attn_chunk, c);
            pv_tf32<<<dim3(Sdim/128, CHUNK_BH), blk, PV_SM_BYTES>>>(attn_chunk, c);
        }
    }

    gemm1024_tf32<0><<<g_gemm, blk>>>(concat, dense_w, dense_b, out);
}